// round 13
// baseline (speedup 1.0000x reference)
#include <cuda_runtime.h>
#include <cuda_bf16.h>
#include <stdint.h>
#include <math.h>

#define H    2048
#define NH   16
#define NKV  4
#define HD   128
#define S_Q  2048
#define S_E  4096
#define EPS  1e-6f

typedef __nv_bfloat16 bf16;
typedef __nv_bfloat162 bf162;

// ---------------- scratch ----------------
__device__ bf16 g_hsH[S_Q * H],    g_hsL[S_Q * H];
__device__ bf16 g_ehsH[S_E * H],   g_ehsL[S_E * H];
__device__ bf16 g_WqTH[H * H],     g_WqTL[H * H];
__device__ bf16 g_WkTH[512 * H],   g_WkTL[512 * H];
__device__ bf16 g_WvTH[512 * H],   g_WvTL[512 * H];
__device__ bf16 g_WoTH[H * H],     g_WoTL[H * H];
__device__ bf16 g_QH[S_Q * H],     g_QL[S_Q * H];
__device__ bf16 g_KH[S_E * 512],   g_KL[S_E * 512];
__device__ bf16 g_VTH[512 * S_E],  g_VTL[512 * S_E];
__device__ bf16 g_AOH[S_Q * H],    g_AOL[S_Q * H];

// ---------------- helpers ----------------
__device__ __forceinline__ unsigned smaddr(const void* p) {
    return (unsigned)__cvta_generic_to_shared(p);
}
__device__ __forceinline__ void ldm_x4(unsigned& r0, unsigned& r1, unsigned& r2, unsigned& r3,
                                       unsigned addr) {
    asm volatile("ldmatrix.sync.aligned.m8n8.x4.shared.b16 {%0,%1,%2,%3},[%4];\n"
                 : "=r"(r0), "=r"(r1), "=r"(r2), "=r"(r3) : "r"(addr));
}
__device__ __forceinline__ void ldm_x2(unsigned& r0, unsigned& r1, unsigned addr) {
    asm volatile("ldmatrix.sync.aligned.m8n8.x2.shared.b16 {%0,%1},[%2];\n"
                 : "=r"(r0), "=r"(r1) : "r"(addr));
}
__device__ __forceinline__ void mma16816(float* c, unsigned a0, unsigned a1, unsigned a2,
                                         unsigned a3, unsigned b0, unsigned b1) {
    asm volatile(
        "mma.sync.aligned.m16n8k16.row.col.f32.bf16.bf16.f32 "
        "{%0,%1,%2,%3},{%4,%5,%6,%7},{%8,%9},{%0,%1,%2,%3};\n"
        : "+f"(c[0]), "+f"(c[1]), "+f"(c[2]), "+f"(c[3])
        : "r"(a0), "r"(a1), "r"(a2), "r"(a3), "r"(b0), "r"(b1));
}
__device__ __forceinline__ void mma3(float* c, const unsigned* ah, const unsigned* al,
                                     unsigned bh0, unsigned bh1, unsigned bl0, unsigned bl1) {
    mma16816(c, ah[0], ah[1], ah[2], ah[3], bh0, bh1);
    mma16816(c, ah[0], ah[1], ah[2], ah[3], bl0, bl1);
    mma16816(c, al[0], al[1], al[2], al[3], bh0, bh1);
}
__device__ __forceinline__ void split2(float x, float y, unsigned& hi, unsigned& lo) {
    bf162 h; h.x = __float2bfloat16(x); h.y = __float2bfloat16(y);
    bf162 l; l.x = __float2bfloat16(x - __bfloat162float(h.x));
    l.y = __float2bfloat16(y - __bfloat162float(h.y));
    hi = *(unsigned*)&h; lo = *(unsigned*)&l;
}
__device__ __forceinline__ void cp16(unsigned saddr, const void* g) {
    asm volatile("cp.async.cg.shared.global [%0], [%1], 16;" :: "r"(saddr), "l"(g));
}
#define CP_COMMIT() asm volatile("cp.async.commit_group;" ::: "memory")
#define CP_WAIT1()  asm volatile("cp.async.wait_group 1;" ::: "memory")

// ---------------- prepass 1: split both activations ----------------
#define NQ4 (S_Q * H / 4)
#define NE4 (S_E * H / 4)
__global__ __launch_bounds__(256) void conv_split_all(
    const float* __restrict__ hs, const float* __restrict__ ehs,
    bf16* __restrict__ hsH, bf16* __restrict__ hsL,
    bf16* __restrict__ ehsH, bf16* __restrict__ ehsL)
{
    int i = blockIdx.x * 256 + threadIdx.x;
    const float* X; bf16 *Xh, *Xl;
    if (i < NQ4) { X = hs; Xh = hsH; Xl = hsL; }
    else { i -= NQ4; if (i >= NE4) return; X = ehs; Xh = ehsH; Xl = ehsL; }
    float4 v = *(const float4*)&X[(size_t)i * 4];
    unsigned h0, l0, h1, l1;
    split2(v.x, v.y, h0, l0);
    split2(v.z, v.w, h1, l1);
    float2 ho, lo;
    ((unsigned*)&ho)[0] = h0; ((unsigned*)&ho)[1] = h1;
    ((unsigned*)&lo)[0] = l0; ((unsigned*)&lo)[1] = l1;
    *(float2*)&Xh[(size_t)i * 4] = ho;
    *(float2*)&Xl[(size_t)i * 4] = lo;
}

// ---------------- prepass 2: transpose+split two weights per launch ----------------
__global__ __launch_bounds__(256) void convT2(
    const float* __restrict__ W0, int N0, bf16* __restrict__ T0h, bf16* __restrict__ T0l,
    const float* __restrict__ W1, int N1, bf16* __restrict__ T1h, bf16* __restrict__ T1l)
{
    const float* W; bf16 *Th, *Tl; int N;
    if (blockIdx.z == 0) { W = W0; Th = T0h; Tl = T0l; N = N0; }
    else { W = W1; Th = T1h; Tl = T1l; N = N1; }
    const int n0 = blockIdx.x * 32;
    if (n0 >= N) return;
    const int k0 = blockIdx.y * 32;
    __shared__ float t[32][33];
    const int tx = threadIdx.x & 31;
    const int ty = threadIdx.x >> 5;
#pragma unroll
    for (int i = 0; i < 4; i++)
        t[ty + 8 * i][tx] = W[(size_t)(k0 + ty + 8 * i) * N + n0 + tx];
    __syncthreads();
#pragma unroll
    for (int i = 0; i < 4; i++) {
        int n = ty + 8 * i;
        float v = t[tx][n];
        bf16 h = __float2bfloat16(v);
        Th[(size_t)(n0 + n) * H + k0 + tx] = h;
        Tl[(size_t)(n0 + n) * H + k0 + tx] = __float2bfloat16(v - __bfloat162float(h));
    }
}

// ---------------- GEMM core: cp.async 2-stage double-buffer, bf16x3 ----------------
// stage layout (bytes): Ahi@0, Alo@10240, Bhi@20480, Blo@30720; row pitch 80B
#define GD_STG  40960
#define GD_SMEM (2 * GD_STG)

__device__ __forceinline__ void gemm_core(
    const bf16* __restrict__ Ahi, const bf16* __restrict__ Alo,
    const bf16* __restrict__ Bhi, const bf16* __restrict__ Blo,
    const float* __restrict__ bias, const float* __restrict__ nw,
    float* __restrict__ Cf, bf16* __restrict__ Chi, bf16* __restrict__ Clo,
    int M, int N, int K, int mode, int vt_stride, char* smc, float* ssq)
{
    const unsigned su = smaddr(smc);
    const int tid  = threadIdx.x;
    const int lane = tid & 31;
    const int warp = tid >> 5;
    const int wm   = warp >> 2;
    const int wn   = warp & 3;
    const int g    = lane >> 2;
    const int th   = lane & 3;
    const int m0   = blockIdx.y * 128;
    const int n0   = blockIdx.x * 128;

    // loader: thread -> row tid>>1, 32B half (tid&1)
    const int lrow  = tid >> 1;
    const int lhalf = (tid & 1) * 32;                       // bytes within 64B row
    const size_t gA = (size_t)(m0 + lrow) * K + lhalf / 2;  // bf16 elems
    const size_t gB = (size_t)(n0 + lrow) * K + lhalf / 2;
    const unsigned soff = lrow * 80 + lhalf;

#define GD_ISSUE(slot, kt) do {                                  \
        unsigned sb_ = su + (slot) * GD_STG;                     \
        size_t ko_ = (size_t)(kt) * 32;                          \
        cp16(sb_ + soff,              Ahi + gA + ko_);           \
        cp16(sb_ + soff + 16,         Ahi + gA + ko_ + 8);       \
        cp16(sb_ + 10240 + soff,      Alo + gA + ko_);           \
        cp16(sb_ + 10240 + soff + 16, Alo + gA + ko_ + 8);       \
        cp16(sb_ + 20480 + soff,      Bhi + gB + ko_);           \
        cp16(sb_ + 20480 + soff + 16, Bhi + gB + ko_ + 8);       \
        cp16(sb_ + 30720 + soff,      Blo + gB + ko_);           \
        cp16(sb_ + 30720 + soff + 16, Blo + gB + ko_ + 8);       \
    } while (0)

    float acc[4][4][4];
#pragma unroll
    for (int i = 0; i < 4; i++)
#pragma unroll
        for (int j = 0; j < 4; j++)
#pragma unroll
            for (int c = 0; c < 4; c++) acc[i][j][c] = 0.f;

    GD_ISSUE(0, 0); CP_COMMIT();
    GD_ISSUE(1, 1); CP_COMMIT();

    const int nK = K / 32;
    for (int kt = 0; kt < nK; kt++) {
        CP_WAIT1();
        __syncthreads();
        const unsigned sb = su + (kt & 1) * GD_STG;
#pragma unroll
        for (int ks = 0; ks < 2; ks++) {
            unsigned ahi[4][4], alo[4][4];
            const int rowl = wm * 64 + (lane & 15);
            const unsigned acol = (ks * 8 + (lane >> 4) * 4) * 4;   // bytes
#pragma unroll
            for (int mt = 0; mt < 4; mt++) {
                ldm_x4(ahi[mt][0], ahi[mt][1], ahi[mt][2], ahi[mt][3],
                       sb + (rowl + mt * 16) * 80 + acol);
                ldm_x4(alo[mt][0], alo[mt][1], alo[mt][2], alo[mt][3],
                       sb + 10240 + (rowl + mt * 16) * 80 + acol);
            }
            const int rowb = lane & 7;
            const unsigned bcol = (ks * 8 + ((lane >> 3) & 1) * 4) * 4;
#pragma unroll
            for (int nt = 0; nt < 4; nt++) {
                unsigned bh0, bh1, bl0, bl1;
                ldm_x2(bh0, bh1, sb + 20480 + (wn * 32 + nt * 8 + rowb) * 80 + bcol);
                ldm_x2(bl0, bl1, sb + 30720 + (wn * 32 + nt * 8 + rowb) * 80 + bcol);
#pragma unroll
                for (int mt = 0; mt < 4; mt++)
                    mma3(acc[mt][nt], ahi[mt], alo[mt], bh0, bh1, bl0, bl1);
            }
        }
        __syncthreads();
        if (kt + 2 < nK) GD_ISSUE(kt & 1, kt + 2);
        CP_COMMIT();
    }
#undef GD_ISSUE

    if (bias) {
#pragma unroll
        for (int nt = 0; nt < 4; nt++) {
            int cc = n0 + wn * 32 + nt * 8 + th * 2;
            float b0 = bias[cc], b1 = bias[cc + 1];
#pragma unroll
            for (int mt = 0; mt < 4; mt++) {
                acc[mt][nt][0] += b0; acc[mt][nt][1] += b1;
                acc[mt][nt][2] += b0; acc[mt][nt][3] += b1;
            }
        }
    }

    if (mode == 0) {
#pragma unroll
        for (int mt = 0; mt < 4; mt++) {
            int r0 = m0 + wm * 64 + mt * 16 + g;
#pragma unroll
            for (int nt = 0; nt < 4; nt++) {
                int cc = n0 + wn * 32 + nt * 8 + th * 2;
                *(float2*)&Cf[(size_t)r0 * N + cc] = make_float2(acc[mt][nt][0], acc[mt][nt][1]);
                *(float2*)&Cf[(size_t)(r0 + 8) * N + cc] = make_float2(acc[mt][nt][2], acc[mt][nt][3]);
            }
        }
    } else if (mode == 1) {
        if (tid < 128) ssq[tid] = 0.f;
        __syncthreads();
#pragma unroll
        for (int mt = 0; mt < 4; mt++) {
            int rl = wm * 64 + mt * 16 + g;
            float p0 = 0.f, p1 = 0.f;
#pragma unroll
            for (int nt = 0; nt < 4; nt++) {
                p0 += acc[mt][nt][0] * acc[mt][nt][0] + acc[mt][nt][1] * acc[mt][nt][1];
                p1 += acc[mt][nt][2] * acc[mt][nt][2] + acc[mt][nt][3] * acc[mt][nt][3];
            }
            atomicAdd(&ssq[rl], p0);
            atomicAdd(&ssq[rl + 8], p1);
        }
        __syncthreads();
#pragma unroll
        for (int mt = 0; mt < 4; mt++) {
            int rl = wm * 64 + mt * 16 + g;
            float inv0 = rsqrtf(ssq[rl] * (1.0f / HD) + EPS);
            float inv1 = rsqrtf(ssq[rl + 8] * (1.0f / HD) + EPS);
#pragma unroll
            for (int nt = 0; nt < 4; nt++) {
                int col = wn * 32 + nt * 8 + th * 2;
                float w0 = nw[col], w1 = nw[col + 1];
                unsigned hh, ll;
                split2(acc[mt][nt][0] * inv0 * w0, acc[mt][nt][1] * inv0 * w1, hh, ll);
                *(unsigned*)&Chi[(size_t)(m0 + rl) * N + n0 + col] = hh;
                *(unsigned*)&Clo[(size_t)(m0 + rl) * N + n0 + col] = ll;
                split2(acc[mt][nt][2] * inv1 * w0, acc[mt][nt][3] * inv1 * w1, hh, ll);
                *(unsigned*)&Chi[(size_t)(m0 + rl + 8) * N + n0 + col] = hh;
                *(unsigned*)&Clo[(size_t)(m0 + rl + 8) * N + n0 + col] = ll;
            }
        }
    } else {
#pragma unroll
        for (int mt = 0; mt < 4; mt++) {
            int r0 = m0 + wm * 64 + mt * 16 + g;
#pragma unroll
            for (int nt = 0; nt < 4; nt++) {
                int cn = n0 + wn * 32 + nt * 8 + th * 2;
#pragma unroll
                for (int j = 0; j < 2; j++) {
                    float v0 = acc[mt][nt][j];
                    float v1 = acc[mt][nt][2 + j];
                    bf16 h0 = __float2bfloat16(v0);
                    bf16 h1 = __float2bfloat16(v1);
                    Chi[(size_t)(cn + j) * vt_stride + r0] = h0;
                    Chi[(size_t)(cn + j) * vt_stride + r0 + 8] = h1;
                    Clo[(size_t)(cn + j) * vt_stride + r0] =
                        __float2bfloat16(v0 - __bfloat162float(h0));
                    Clo[(size_t)(cn + j) * vt_stride + r0 + 8] =
                        __float2bfloat16(v1 - __bfloat162float(h1));
                }
            }
        }
    }
}

__global__ __launch_bounds__(256, 2) void gemm_db(
    const bf16* Ahi, const bf16* Alo, const bf16* Bhi, const bf16* Blo,
    const float* bias, const float* nw,
    float* Cf, bf16* Chi, bf16* Clo,
    int M, int N, int K, int mode, int vt_stride)
{
    extern __shared__ char smc[];
    __shared__ float ssq[128];
    gemm_core(Ahi, Alo, Bhi, Blo, bias, nw, Cf, Chi, Clo, M, N, K, mode, vt_stride, smc, ssq);
}

__global__ __launch_bounds__(256, 2) void gemm_kv(
    const bf16* Ahi, const bf16* Alo,
    const bf16* Bkh, const bf16* Bkl, const float* bk, const float* kn,
    bf16* KH, bf16* KL,
    const bf16* Bvh, const bf16* Bvl, const float* bv,
    bf16* VTH, bf16* VTL)
{
    extern __shared__ char smc[];
    __shared__ float ssq[128];
    if (blockIdx.z == 0)
        gemm_core(Ahi, Alo, Bkh, Bkl, bk, kn, nullptr, KH, KL, S_E, 512, H, 1, 0, smc, ssq);
    else
        gemm_core(Ahi, Alo, Bvh, Bvl, bv, nullptr, nullptr, VTH, VTL, S_E, 512, H, 2, S_E, smc, ssq);
}

// ---------------- flash: 3-slot cp.async pipeline, Q in regs ----------------
// slot layout (bytes): Khi@0 (64 rows x 272B), Klo@17408, Vhi@34816 (128 x 144B), Vlo@53248
#define FV_KB   17408
#define FV_VB   18432
#define FV_STG  71680
#define FV_SMEM (3 * FV_STG)

__global__ __launch_bounds__(256, 1) void flash_x3d(
    const bf16* __restrict__ Qhi, const bf16* __restrict__ Qlo,
    const bf16* __restrict__ Khi, const bf16* __restrict__ Klo,
    const bf16* __restrict__ VThi, const bf16* __restrict__ VTlo,
    const float* __restrict__ mask,
    bf16* __restrict__ AOhi, bf16* __restrict__ AOlo)
{
    extern __shared__ char smf[];
    const unsigned su = smaddr(smf);
    const int h  = blockIdx.y;
    const int kh = h >> 2;
    const int q0 = blockIdx.x * 128;
    const int tid  = threadIdx.x;
    const int lane = tid & 31;
    const int w    = tid >> 5;
    const int g    = lane >> 2;
    const int th   = lane & 3;

#define FV_ISSUE(slot, et) do {                                             \
        const unsigned sb_ = su + (slot) * FV_STG;                          \
        const int e0_ = (et) * 64;                                          \
        _Pragma("unroll")                                                   \
        for (int l = 0; l < 4; l++) {                                       \
            int ch = l * 256 + tid;                                         \
            int kr = ch >> 4, kc = ch & 15;                                 \
            size_t gk = (size_t)(e0_ + kr) * 512 + kh * 128 + kc * 8;       \
            cp16(sb_ + kr * 272 + kc * 16,          Khi + gk);              \
            cp16(sb_ + FV_KB + kr * 272 + kc * 16,  Klo + gk);              \
            int vr = ch >> 3, vc = ch & 7;                                  \
            size_t gv = (size_t)(kh * 128 + vr) * S_E + e0_ + vc * 8;       \
            cp16(sb_ + 2 * FV_KB + vr * 144 + vc * 16,         VThi + gv);  \
            cp16(sb_ + 2 * FV_KB + FV_VB + vr * 144 + vc * 16, VTlo + gv);  \
        }                                                                   \
    } while (0)

    FV_ISSUE(0, 0); CP_COMMIT();
    FV_ISSUE(1, 1); CP_COMMIT();

    // Q fragments in registers
    unsigned qh[8][4], ql[8][4];
    {
        const size_t rq0 = (size_t)(q0 + w * 16 + g) * (NH * HD) + h * HD;
        const size_t rq8 = rq0 + (size_t)8 * (NH * HD);
#pragma unroll
        for (int ks = 0; ks < 8; ks++) {
            const int c = ks * 16 + th * 2;
            qh[ks][0] = *(const unsigned*)&Qhi[rq0 + c];
            qh[ks][1] = *(const unsigned*)&Qhi[rq8 + c];
            qh[ks][2] = *(const unsigned*)&Qhi[rq0 + c + 8];
            qh[ks][3] = *(const unsigned*)&Qhi[rq8 + c + 8];
            ql[ks][0] = *(const unsigned*)&Qlo[rq0 + c];
            ql[ks][1] = *(const unsigned*)&Qlo[rq8 + c];
            ql[ks][2] = *(const unsigned*)&Qlo[rq0 + c + 8];
            ql[ks][3] = *(const unsigned*)&Qlo[rq8 + c + 8];
        }
    }

    const float scale = 0.08838834764831845f;
    float o[16][4];
    float m0i = -INFINITY, m1i = -INFINITY, l0i = 0.f, l1i = 0.f;
#pragma unroll
    for (int nt = 0; nt < 16; nt++)
#pragma unroll
        for (int c = 0; c < 4; c++) o[nt][c] = 0.f;

    const int r0 = q0 + w * 16 + g;

    for (int et = 0; et < S_E / 64; et++) {
        CP_WAIT1();
        __syncthreads();
        if (et + 2 < S_E / 64) FV_ISSUE((et + 2) % 3, et + 2);
        CP_COMMIT();

        const unsigned sb = su + (et % 3) * FV_STG;
        const int e0 = et * 64;

        // ---- S = Q K^T ----
        float s[8][4];
#pragma unroll
        for (int nt = 0; nt < 8; nt++)
#pragma unroll
            for (int c = 0; c < 4; c++) s[nt][c] = 0.f;

#pragma unroll
        for (int ks = 0; ks < 8; ks++) {
            const int rowb = lane & 7;
            const unsigned bcol = (ks * 8 + ((lane >> 3) & 1) * 4) * 4;
#pragma unroll
            for (int nt = 0; nt < 8; nt++) {
                unsigned bh0, bh1, bl0, bl1;
                ldm_x2(bh0, bh1, sb + (nt * 8 + rowb) * 272 + bcol);
                ldm_x2(bl0, bl1, sb + FV_KB + (nt * 8 + rowb) * 272 + bcol);
                mma3(s[nt], qh[ks], ql[ks], bh0, bh1, bl0, bl1);
            }
        }

        // ---- scale + mask + online softmax ----
#pragma unroll
        for (int nt = 0; nt < 8; nt++) {
            const int cbm = e0 + nt * 8 + th * 2;
            float2 mk0 = *(const float2*)&mask[(size_t)r0 * S_E + cbm];
            float2 mk1 = *(const float2*)&mask[(size_t)(r0 + 8) * S_E + cbm];
            s[nt][0] = s[nt][0] * scale + mk0.x;
            s[nt][1] = s[nt][1] * scale + mk0.y;
            s[nt][2] = s[nt][2] * scale + mk1.x;
            s[nt][3] = s[nt][3] * scale + mk1.y;
        }
        float mx0 = -INFINITY, mx1 = -INFINITY;
#pragma unroll
        for (int nt = 0; nt < 8; nt++) {
            mx0 = fmaxf(mx0, fmaxf(s[nt][0], s[nt][1]));
            mx1 = fmaxf(mx1, fmaxf(s[nt][2], s[nt][3]));
        }
        mx0 = fmaxf(mx0, __shfl_xor_sync(0xffffffffu, mx0, 1));
        mx0 = fmaxf(mx0, __shfl_xor_sync(0xffffffffu, mx0, 2));
        mx1 = fmaxf(mx1, __shfl_xor_sync(0xffffffffu, mx1, 1));
        mx1 = fmaxf(mx1, __shfl_xor_sync(0xffffffffu, mx1, 2));
        float mn0 = fmaxf(m0i, mx0);
        float mn1 = fmaxf(m1i, mx1);
        float cr0 = __expf(m0i - mn0);
        float cr1 = __expf(m1i - mn1);
        m0i = mn0; m1i = mn1;
        float sm0 = 0.f, sm1 = 0.f;
#pragma unroll
        for (int nt = 0; nt < 8; nt++) {
            s[nt][0] = __expf(s[nt][0] - mn0);
            s[nt][1] = __expf(s[nt][1] - mn0);
            s[nt][2] = __expf(s[nt][2] - mn1);
            s[nt][3] = __expf(s[nt][3] - mn1);
            sm0 += s[nt][0] + s[nt][1];
            sm1 += s[nt][2] + s[nt][3];
        }
        sm0 += __shfl_xor_sync(0xffffffffu, sm0, 1);
        sm0 += __shfl_xor_sync(0xffffffffu, sm0, 2);
        sm1 += __shfl_xor_sync(0xffffffffu, sm1, 1);
        sm1 += __shfl_xor_sync(0xffffffffu, sm1, 2);
        l0i = l0i * cr0 + sm0;
        l1i = l1i * cr1 + sm1;
#pragma unroll
        for (int nt = 0; nt < 16; nt++) {
            o[nt][0] *= cr0;
            o[nt][1] *= cr0;
            o[nt][2] *= cr1;
            o[nt][3] *= cr1;
        }

        // ---- O += P V ----
#pragma unroll
        for (int ks2 = 0; ks2 < 4; ks2++) {
            unsigned phi[4], plo[4];
            const float* sa = s[2 * ks2];
            const float* sbp = s[2 * ks2 + 1];
            split2(sa[0], sa[1], phi[0], plo[0]);
            split2(sa[2], sa[3], phi[1], plo[1]);
            split2(sbp[0], sbp[1], phi[2], plo[2]);
            split2(sbp[2], sbp[3], phi[3], plo[3]);
            const int rowv = lane & 7;
            const unsigned vcol = (ks2 * 8 + ((lane >> 3) & 1) * 4) * 4;
#pragma unroll
            for (int nt2 = 0; nt2 < 16; nt2++) {
                unsigned vh0, vh1, vl0, vl1;
                ldm_x2(vh0, vh1, sb + 2 * FV_KB + (nt2 * 8 + rowv) * 144 + vcol);
                ldm_x2(vl0, vl1, sb + 2 * FV_KB + FV_VB + (nt2 * 8 + rowv) * 144 + vcol);
                mma3(o[nt2], phi, plo, vh0, vh1, vl0, vl1);
            }
        }
    }
#undef FV_ISSUE

    // ---- epilogue ----
    const float inv0 = 1.0f / l0i;
    const float inv1 = 1.0f / l1i;
#pragma unroll
    for (int nt2 = 0; nt2 < 16; nt2++) {
        const int cc = h * HD + nt2 * 8 + th * 2;
        unsigned hh, ll;
        split2(o[nt2][0] * inv0, o[nt2][1] * inv0, hh, ll);
        *(unsigned*)&AOhi[(size_t)r0 * (NH * HD) + cc] = hh;
        *(unsigned*)&AOlo[(size_t)r0 * (NH * HD) + cc] = ll;
        split2(o[nt2][2] * inv1, o[nt2][3] * inv1, hh, ll);
        *(unsigned*)&AOhi[(size_t)(r0 + 8) * (NH * HD) + cc] = hh;
        *(unsigned*)&AOlo[(size_t)(r0 + 8) * (NH * HD) + cc] = ll;
    }
}

// ---------------- launch ----------------
#define SYM(p, s) cudaGetSymbolAddress((void**)&p, s)

extern "C" void kernel_launch(void* const* d_in, const int* in_sizes, int n_in,
                              void* d_out, int out_size)
{
    const float* hs   = (const float*)d_in[0];
    const float* ehs  = (const float*)d_in[1];
    const float* mask = (const float*)d_in[2];
    const float* Wq   = (const float*)d_in[3];
    const float* bq   = (const float*)d_in[4];
    const float* Wk   = (const float*)d_in[5];
    const float* bk   = (const float*)d_in[6];
    const float* Wv   = (const float*)d_in[7];
    const float* bv   = (const float*)d_in[8];
    const float* Wo   = (const float*)d_in[9];
    const float* qn   = (const float*)d_in[10];
    const float* kn   = (const float*)d_in[11];
    float* out = (float*)d_out;

    bf16 *hsH, *hsL, *ehsH, *ehsL, *WqTH, *WqTL, *WkTH, *WkTL, *WvTH, *WvTL, *WoTH, *WoTL;
    bf16 *QH, *QL, *KH, *KL, *VTH, *VTL, *AOH, *AOL;
    SYM(hsH, g_hsH);  SYM(hsL, g_hsL);
    SYM(ehsH, g_ehsH); SYM(ehsL, g_ehsL);
    SYM(WqTH, g_WqTH); SYM(WqTL, g_WqTL);
    SYM(WkTH, g_WkTH); SYM(WkTL, g_WkTL);
    SYM(WvTH, g_WvTH); SYM(WvTL, g_WvTL);
    SYM(WoTH, g_WoTH); SYM(WoTL, g_WoTL);
    SYM(QH, g_QH); SYM(QL, g_QL);
    SYM(KH, g_KH); SYM(KL, g_KL);
    SYM(VTH, g_VTH); SYM(VTL, g_VTL);
    SYM(AOH, g_AOH); SYM(AOL, g_AOL);

    cudaFuncSetAttribute(gemm_db, cudaFuncAttributeMaxDynamicSharedMemorySize, GD_SMEM);
    cudaFuncSetAttribute(gemm_kv, cudaFuncAttributeMaxDynamicSharedMemorySize, GD_SMEM);
    cudaFuncSetAttribute(flash_x3d, cudaFuncAttributeMaxDynamicSharedMemorySize, FV_SMEM);

    // 0: activations split
    conv_split_all<<<(NQ4 + NE4 + 255) / 256, 256>>>(hs, ehs, hsH, hsL, ehsH, ehsL);
    // 1: Wq + Wo transpose/split
    convT2<<<dim3(64, 64, 2), 256>>>(Wq, 2048, WqTH, WqTL, Wo, 2048, WoTH, WoTL);
    // 2: Wk + Wv transpose/split
    convT2<<<dim3(16, 64, 2), 256>>>(Wk, 512, WkTH, WkTL, Wv, 512, WvTH, WvTL);
    // 3: Q projection (rmsnorm fused)
    gemm_db<<<dim3(16, 16), 256, GD_SMEM>>>(hsH, hsL, WqTH, WqTL, bq, qn,
                                            nullptr, QH, QL, S_Q, H, H, 1, 0);
    // 4: K + V projections merged
    gemm_kv<<<dim3(4, 32, 2), 256, GD_SMEM>>>(ehsH, ehsL,
                                              WkTH, WkTL, bk, kn, KH, KL,
                                              WvTH, WvTL, bv, VTH, VTL);
    // 5: attention (ncu -s 5 profiles this)
    flash_x3d<<<dim3(S_Q / 128, NH), 256, FV_SMEM>>>(QH, QL, KH, KL, VTH, VTL,
                                                     mask, AOH, AOL);
    // 6: output projection
    gemm_db<<<dim3(16, 16), 256, GD_SMEM>>>(AOH, AOL, WoTH, WoTL, nullptr, nullptr,
                                            out, nullptr, nullptr, S_Q, H, NH * HD, 0, 0);
}

// round 14
// speedup vs baseline: 1.0063x; 1.0063x over previous
#include <cuda_runtime.h>
#include <cuda_bf16.h>
#include <stdint.h>
#include <math.h>

#define H    2048
#define NH   16
#define NKV  4
#define HD   128
#define S_Q  2048
#define S_E  4096
#define EPS  1e-6f

typedef __nv_bfloat16 bf16;
typedef __nv_bfloat162 bf162;

// ---------------- scratch ----------------
__device__ bf16 g_hsH[S_Q * H],    g_hsL[S_Q * H];
__device__ bf16 g_ehsH[S_E * H],   g_ehsL[S_E * H];
__device__ bf16 g_WqTH[H * H],     g_WqTL[H * H];
__device__ bf16 g_WkTH[512 * H],   g_WkTL[512 * H];
__device__ bf16 g_WvTH[512 * H],   g_WvTL[512 * H];
__device__ bf16 g_WoTH[H * H],     g_WoTL[H * H];
__device__ bf16 g_QH[S_Q * H],     g_QL[S_Q * H];
__device__ bf16 g_KH[S_E * 512],   g_KL[S_E * 512];
__device__ bf16 g_VTH[512 * S_E],  g_VTL[512 * S_E];
__device__ bf16 g_AOH[S_Q * H],    g_AOL[S_Q * H];

// ---------------- helpers ----------------
__device__ __forceinline__ unsigned smaddr(const void* p) {
    return (unsigned)__cvta_generic_to_shared(p);
}
__device__ __forceinline__ void ldm_x4(unsigned& r0, unsigned& r1, unsigned& r2, unsigned& r3,
                                       unsigned addr) {
    asm volatile("ldmatrix.sync.aligned.m8n8.x4.shared.b16 {%0,%1,%2,%3},[%4];\n"
                 : "=r"(r0), "=r"(r1), "=r"(r2), "=r"(r3) : "r"(addr));
}
__device__ __forceinline__ void ldm_x2(unsigned& r0, unsigned& r1, unsigned addr) {
    asm volatile("ldmatrix.sync.aligned.m8n8.x2.shared.b16 {%0,%1},[%2];\n"
                 : "=r"(r0), "=r"(r1) : "r"(addr));
}
__device__ __forceinline__ void mma16816(float* c, unsigned a0, unsigned a1, unsigned a2,
                                         unsigned a3, unsigned b0, unsigned b1) {
    asm volatile(
        "mma.sync.aligned.m16n8k16.row.col.f32.bf16.bf16.f32 "
        "{%0,%1,%2,%3},{%4,%5,%6,%7},{%8,%9},{%0,%1,%2,%3};\n"
        : "+f"(c[0]), "+f"(c[1]), "+f"(c[2]), "+f"(c[3])
        : "r"(a0), "r"(a1), "r"(a2), "r"(a3), "r"(b0), "r"(b1));
}
__device__ __forceinline__ void mma3(float* c, const unsigned* ah, const unsigned* al,
                                     unsigned bh0, unsigned bh1, unsigned bl0, unsigned bl1) {
    mma16816(c, ah[0], ah[1], ah[2], ah[3], bh0, bh1);
    mma16816(c, ah[0], ah[1], ah[2], ah[3], bl0, bl1);
    mma16816(c, al[0], al[1], al[2], al[3], bh0, bh1);
}
__device__ __forceinline__ void split2(float x, float y, unsigned& hi, unsigned& lo) {
    bf162 h; h.x = __float2bfloat16(x); h.y = __float2bfloat16(y);
    bf162 l; l.x = __float2bfloat16(x - __bfloat162float(h.x));
    l.y = __float2bfloat16(y - __bfloat162float(h.y));
    hi = *(unsigned*)&h; lo = *(unsigned*)&l;
}
__device__ __forceinline__ void cp16(unsigned saddr, const void* g) {
    asm volatile("cp.async.cg.shared.global [%0], [%1], 16;" :: "r"(saddr), "l"(g));
}
#define CP_COMMIT() asm volatile("cp.async.commit_group;" ::: "memory")
#define CP_WAIT1()  asm volatile("cp.async.wait_group 1;" ::: "memory")

// ---------------- prepass 1 ----------------
#define NQ4 (S_Q * H / 4)
#define NE4 (S_E * H / 4)
__global__ __launch_bounds__(256) void conv_split_all(
    const float* __restrict__ hs, const float* __restrict__ ehs,
    bf16* __restrict__ hsH, bf16* __restrict__ hsL,
    bf16* __restrict__ ehsH, bf16* __restrict__ ehsL)
{
    int i = blockIdx.x * 256 + threadIdx.x;
    const float* X; bf16 *Xh, *Xl;
    if (i < NQ4) { X = hs; Xh = hsH; Xl = hsL; }
    else { i -= NQ4; if (i >= NE4) return; X = ehs; Xh = ehsH; Xl = ehsL; }
    float4 v = *(const float4*)&X[(size_t)i * 4];
    unsigned h0, l0, h1, l1;
    split2(v.x, v.y, h0, l0);
    split2(v.z, v.w, h1, l1);
    float2 ho, lo;
    ((unsigned*)&ho)[0] = h0; ((unsigned*)&ho)[1] = h1;
    ((unsigned*)&lo)[0] = l0; ((unsigned*)&lo)[1] = l1;
    *(float2*)&Xh[(size_t)i * 4] = ho;
    *(float2*)&Xl[(size_t)i * 4] = lo;
}

// ---------------- prepass 2: all 4 weights ----------------
__global__ __launch_bounds__(256) void convT_all(
    const float* __restrict__ Wq, const float* __restrict__ Wk,
    const float* __restrict__ Wv, const float* __restrict__ Wo,
    bf16* __restrict__ qTh, bf16* __restrict__ qTl,
    bf16* __restrict__ kTh, bf16* __restrict__ kTl,
    bf16* __restrict__ vTh, bf16* __restrict__ vTl,
    bf16* __restrict__ oTh, bf16* __restrict__ oTl)
{
    const float* W; bf16 *Th, *Tl; int N;
    switch (blockIdx.z) {
        case 0: W = Wq; Th = qTh; Tl = qTl; N = 2048; break;
        case 1: W = Wk; Th = kTh; Tl = kTl; N = 512; break;
        case 2: W = Wv; Th = vTh; Tl = vTl; N = 512; break;
        default: W = Wo; Th = oTh; Tl = oTl; N = 2048; break;
    }
    const int n0 = blockIdx.x * 32;
    if (n0 >= N) return;
    const int k0 = blockIdx.y * 32;
    __shared__ float t[32][33];
    const int tx = threadIdx.x & 31;
    const int ty = threadIdx.x >> 5;
#pragma unroll
    for (int i = 0; i < 4; i++)
        t[ty + 8 * i][tx] = W[(size_t)(k0 + ty + 8 * i) * N + n0 + tx];
    __syncthreads();
#pragma unroll
    for (int i = 0; i < 4; i++) {
        int n = ty + 8 * i;
        float v = t[tx][n];
        bf16 h = __float2bfloat16(v);
        Th[(size_t)(n0 + n) * H + k0 + tx] = h;
        Tl[(size_t)(n0 + n) * H + k0 + tx] = __float2bfloat16(v - __bfloat162float(h));
    }
}

// ---------------- GEMM core (explicit m0/n0) ----------------
#define GD_STG  40960
#define GD_SMEM (2 * GD_STG)

__device__ __forceinline__ void gemm_core(
    const bf16* __restrict__ Ahi, const bf16* __restrict__ Alo,
    const bf16* __restrict__ Bhi, const bf16* __restrict__ Blo,
    const float* __restrict__ bias, const float* __restrict__ nw,
    float* __restrict__ Cf, bf16* __restrict__ Chi, bf16* __restrict__ Clo,
    int N, int K, int mode, int vt_stride, int m0, int n0, char* smc, float* ssq)
{
    const unsigned su = smaddr(smc);
    const int tid  = threadIdx.x;
    const int lane = tid & 31;
    const int warp = tid >> 5;
    const int wm   = warp >> 2;
    const int wn   = warp & 3;
    const int g    = lane >> 2;
    const int th   = lane & 3;

    const int lrow  = tid >> 1;
    const int lhalf = (tid & 1) * 32;
    const size_t gA = (size_t)(m0 + lrow) * K + lhalf / 2;
    const size_t gB = (size_t)(n0 + lrow) * K + lhalf / 2;
    const unsigned soff = lrow * 80 + lhalf;

#define GD_ISSUE(slot, kt) do {                                  \
        unsigned sb_ = su + (slot) * GD_STG;                     \
        size_t ko_ = (size_t)(kt) * 32;                          \
        cp16(sb_ + soff,              Ahi + gA + ko_);           \
        cp16(sb_ + soff + 16,         Ahi + gA + ko_ + 8);       \
        cp16(sb_ + 10240 + soff,      Alo + gA + ko_);           \
        cp16(sb_ + 10240 + soff + 16, Alo + gA + ko_ + 8);       \
        cp16(sb_ + 20480 + soff,      Bhi + gB + ko_);           \
        cp16(sb_ + 20480 + soff + 16, Bhi + gB + ko_ + 8);       \
        cp16(sb_ + 30720 + soff,      Blo + gB + ko_);           \
        cp16(sb_ + 30720 + soff + 16, Blo + gB + ko_ + 8);       \
    } while (0)

    float acc[4][4][4];
#pragma unroll
    for (int i = 0; i < 4; i++)
#pragma unroll
        for (int j = 0; j < 4; j++)
#pragma unroll
            for (int c = 0; c < 4; c++) acc[i][j][c] = 0.f;

    GD_ISSUE(0, 0); CP_COMMIT();
    GD_ISSUE(1, 1); CP_COMMIT();

    const int nK = K / 32;
    for (int kt = 0; kt < nK; kt++) {
        CP_WAIT1();
        __syncthreads();
        const unsigned sb = su + (kt & 1) * GD_STG;
#pragma unroll
        for (int ks = 0; ks < 2; ks++) {
            unsigned ahi[4][4], alo[4][4];
            const int rowl = wm * 64 + (lane & 15);
            const unsigned acol = (ks * 8 + (lane >> 4) * 4) * 4;
#pragma unroll
            for (int mt = 0; mt < 4; mt++) {
                ldm_x4(ahi[mt][0], ahi[mt][1], ahi[mt][2], ahi[mt][3],
                       sb + (rowl + mt * 16) * 80 + acol);
                ldm_x4(alo[mt][0], alo[mt][1], alo[mt][2], alo[mt][3],
                       sb + 10240 + (rowl + mt * 16) * 80 + acol);
            }
            const int rowb = lane & 7;
            const unsigned bcol = (ks * 8 + ((lane >> 3) & 1) * 4) * 4;
#pragma unroll
            for (int nt = 0; nt < 4; nt++) {
                unsigned bh0, bh1, bl0, bl1;
                ldm_x2(bh0, bh1, sb + 20480 + (wn * 32 + nt * 8 + rowb) * 80 + bcol);
                ldm_x2(bl0, bl1, sb + 30720 + (wn * 32 + nt * 8 + rowb) * 80 + bcol);
#pragma unroll
                for (int mt = 0; mt < 4; mt++)
                    mma3(acc[mt][nt], ahi[mt], alo[mt], bh0, bh1, bl0, bl1);
            }
        }
        __syncthreads();
        if (kt + 2 < nK) GD_ISSUE(kt & 1, kt + 2);
        CP_COMMIT();
    }
#undef GD_ISSUE

    if (bias) {
#pragma unroll
        for (int nt = 0; nt < 4; nt++) {
            int cc = n0 + wn * 32 + nt * 8 + th * 2;
            float b0 = bias[cc], b1 = bias[cc + 1];
#pragma unroll
            for (int mt = 0; mt < 4; mt++) {
                acc[mt][nt][0] += b0; acc[mt][nt][1] += b1;
                acc[mt][nt][2] += b0; acc[mt][nt][3] += b1;
            }
        }
    }

    if (mode == 0) {
#pragma unroll
        for (int mt = 0; mt < 4; mt++) {
            int r0 = m0 + wm * 64 + mt * 16 + g;
#pragma unroll
            for (int nt = 0; nt < 4; nt++) {
                int cc = n0 + wn * 32 + nt * 8 + th * 2;
                *(float2*)&Cf[(size_t)r0 * N + cc] = make_float2(acc[mt][nt][0], acc[mt][nt][1]);
                *(float2*)&Cf[(size_t)(r0 + 8) * N + cc] = make_float2(acc[mt][nt][2], acc[mt][nt][3]);
            }
        }
    } else if (mode == 1) {
        if (tid < 128) ssq[tid] = 0.f;
        __syncthreads();
#pragma unroll
        for (int mt = 0; mt < 4; mt++) {
            int rl = wm * 64 + mt * 16 + g;
            float p0 = 0.f, p1 = 0.f;
#pragma unroll
            for (int nt = 0; nt < 4; nt++) {
                p0 += acc[mt][nt][0] * acc[mt][nt][0] + acc[mt][nt][1] * acc[mt][nt][1];
                p1 += acc[mt][nt][2] * acc[mt][nt][2] + acc[mt][nt][3] * acc[mt][nt][3];
            }
            atomicAdd(&ssq[rl], p0);
            atomicAdd(&ssq[rl + 8], p1);
        }
        __syncthreads();
#pragma unroll
        for (int mt = 0; mt < 4; mt++) {
            int rl = wm * 64 + mt * 16 + g;
            float inv0 = rsqrtf(ssq[rl] * (1.0f / HD) + EPS);
            float inv1 = rsqrtf(ssq[rl + 8] * (1.0f / HD) + EPS);
#pragma unroll
            for (int nt = 0; nt < 4; nt++) {
                int col = wn * 32 + nt * 8 + th * 2;
                float w0 = nw[col], w1 = nw[col + 1];
                unsigned hh, ll;
                split2(acc[mt][nt][0] * inv0 * w0, acc[mt][nt][1] * inv0 * w1, hh, ll);
                *(unsigned*)&Chi[(size_t)(m0 + rl) * N + n0 + col] = hh;
                *(unsigned*)&Clo[(size_t)(m0 + rl) * N + n0 + col] = ll;
                split2(acc[mt][nt][2] * inv1 * w0, acc[mt][nt][3] * inv1 * w1, hh, ll);
                *(unsigned*)&Chi[(size_t)(m0 + rl + 8) * N + n0 + col] = hh;
                *(unsigned*)&Clo[(size_t)(m0 + rl + 8) * N + n0 + col] = ll;
            }
        }
    } else {
#pragma unroll
        for (int mt = 0; mt < 4; mt++) {
            int r0 = m0 + wm * 64 + mt * 16 + g;
#pragma unroll
            for (int nt = 0; nt < 4; nt++) {
                int cn = n0 + wn * 32 + nt * 8 + th * 2;
#pragma unroll
                for (int j = 0; j < 2; j++) {
                    float v0 = acc[mt][nt][j];
                    float v1 = acc[mt][nt][2 + j];
                    bf16 h0 = __float2bfloat16(v0);
                    bf16 h1 = __float2bfloat16(v1);
                    Chi[(size_t)(cn + j) * vt_stride + r0] = h0;
                    Chi[(size_t)(cn + j) * vt_stride + r0 + 8] = h1;
                    Clo[(size_t)(cn + j) * vt_stride + r0] =
                        __float2bfloat16(v0 - __bfloat162float(h0));
                    Clo[(size_t)(cn + j) * vt_stride + r0 + 8] =
                        __float2bfloat16(v1 - __bfloat162float(h1));
                }
            }
        }
    }
}

// ---------------- merged Q+K+V projection ----------------
__global__ __launch_bounds__(256, 2) void gemm_qkv(
    const bf16* hsH, const bf16* hsL, const bf16* ehsH, const bf16* ehsL,
    const bf16* WqTH, const bf16* WqTL, const float* bq, const float* qn,
    bf16* QH, bf16* QL,
    const bf16* WkTH, const bf16* WkTL, const float* bk, const float* kn,
    bf16* KH, bf16* KL,
    const bf16* WvTH, const bf16* WvTL, const float* bv,
    bf16* VTH, bf16* VTL)
{
    extern __shared__ char smc[];
    __shared__ float ssq[128];
    if (blockIdx.z == 0) {
        gemm_core(hsH, hsL, WqTH, WqTL, bq, qn, nullptr, QH, QL,
                  H, H, 1, 0, blockIdx.y * 128, blockIdx.x * 128, smc, ssq);
    } else {
        int bid = blockIdx.y * 16 + blockIdx.x;        // 0..255
        int m0 = ((bid & 127) >> 2) * 128;
        int n0 = (bid & 3) * 128;
        if (bid < 128)
            gemm_core(ehsH, ehsL, WkTH, WkTL, bk, kn, nullptr, KH, KL,
                      512, H, 1, 0, m0, n0, smc, ssq);
        else
            gemm_core(ehsH, ehsL, WvTH, WvTL, bv, nullptr, nullptr, VTH, VTL,
                      512, H, 2, S_E, m0, n0, smc, ssq);
    }
}

__global__ __launch_bounds__(256, 2) void gemm_db(
    const bf16* Ahi, const bf16* Alo, const bf16* Bhi, const bf16* Blo,
    const float* bias, const float* nw,
    float* Cf, bf16* Chi, bf16* Clo,
    int N, int K, int mode, int vt_stride)
{
    extern __shared__ char smc[];
    __shared__ float ssq[128];
    gemm_core(Ahi, Alo, Bhi, Blo, bias, nw, Cf, Chi, Clo, N, K, mode, vt_stride,
              blockIdx.y * 128, blockIdx.x * 128, smc, ssq);
}

// ---------------- flash: 3-slot cp.async pipeline, Q in regs ----------------
#define FV_KB   17408
#define FV_VB   18432
#define FV_STG  71680
#define FV_SMEM (3 * FV_STG)

__global__ __launch_bounds__(256, 1) void flash_x3d(
    const bf16* __restrict__ Qhi, const bf16* __restrict__ Qlo,
    const bf16* __restrict__ Khi, const bf16* __restrict__ Klo,
    const bf16* __restrict__ VThi, const bf16* __restrict__ VTlo,
    const float* __restrict__ mask,
    bf16* __restrict__ AOhi, bf16* __restrict__ AOlo)
{
    extern __shared__ char smf[];
    const unsigned su = smaddr(smf);
    const int h  = blockIdx.y;
    const int kh = h >> 2;
    const int q0 = blockIdx.x * 128;
    const int tid  = threadIdx.x;
    const int lane = tid & 31;
    const int w    = tid >> 5;
    const int g    = lane >> 2;
    const int th   = lane & 3;

#define FV_ISSUE(slot, et) do {                                             \
        const unsigned sb_ = su + (slot) * FV_STG;                          \
        const int e0_ = (et) * 64;                                          \
        _Pragma("unroll")                                                   \
        for (int l = 0; l < 4; l++) {                                       \
            int ch = l * 256 + tid;                                         \
            int kr = ch >> 4, kc = ch & 15;                                 \
            size_t gk = (size_t)(e0_ + kr) * 512 + kh * 128 + kc * 8;       \
            cp16(sb_ + kr * 272 + kc * 16,          Khi + gk);              \
            cp16(sb_ + FV_KB + kr * 272 + kc * 16,  Klo + gk);              \
            int vr = ch >> 3, vc = ch & 7;                                  \
            size_t gv = (size_t)(kh * 128 + vr) * S_E + e0_ + vc * 8;       \
            cp16(sb_ + 2 * FV_KB + vr * 144 + vc * 16,         VThi + gv);  \
            cp16(sb_ + 2 * FV_KB + FV_VB + vr * 144 + vc * 16, VTlo + gv);  \
        }                                                                   \
    } while (0)

    FV_ISSUE(0, 0); CP_COMMIT();
    FV_ISSUE(1, 1); CP_COMMIT();

    unsigned qh[8][4], ql[8][4];
    {
        const size_t rq0 = (size_t)(q0 + w * 16 + g) * (NH * HD) + h * HD;
        const size_t rq8 = rq0 + (size_t)8 * (NH * HD);
#pragma unroll
        for (int ks = 0; ks < 8; ks++) {
            const int c = ks * 16 + th * 2;
            qh[ks][0] = *(const unsigned*)&Qhi[rq0 + c];
            qh[ks][1] = *(const unsigned*)&Qhi[rq8 + c];
            qh[ks][2] = *(const unsigned*)&Qhi[rq0 + c + 8];
            qh[ks][3] = *(const unsigned*)&Qhi[rq8 + c + 8];
            ql[ks][0] = *(const unsigned*)&Qlo[rq0 + c];
            ql[ks][1] = *(const unsigned*)&Qlo[rq8 + c];
            ql[ks][2] = *(const unsigned*)&Qlo[rq0 + c + 8];
            ql[ks][3] = *(const unsigned*)&Qlo[rq8 + c + 8];
        }
    }

    const float scale = 0.08838834764831845f;
    float o[16][4];
    float m0i = -INFINITY, m1i = -INFINITY, l0i = 0.f, l1i = 0.f;
#pragma unroll
    for (int nt = 0; nt < 16; nt++)
#pragma unroll
        for (int c = 0; c < 4; c++) o[nt][c] = 0.f;

    const int r0 = q0 + w * 16 + g;

    for (int et = 0; et < S_E / 64; et++) {
        CP_WAIT1();
        __syncthreads();
        if (et + 2 < S_E / 64) FV_ISSUE((et + 2) % 3, et + 2);
        CP_COMMIT();

        const unsigned sb = su + (et % 3) * FV_STG;
        const int e0 = et * 64;

        float s[8][4];
#pragma unroll
        for (int nt = 0; nt < 8; nt++)
#pragma unroll
            for (int c = 0; c < 4; c++) s[nt][c] = 0.f;

#pragma unroll
        for (int ks = 0; ks < 8; ks++) {
            const int rowb = lane & 7;
            const unsigned bcol = (ks * 8 + ((lane >> 3) & 1) * 4) * 4;
#pragma unroll
            for (int nt = 0; nt < 8; nt++) {
                unsigned bh0, bh1, bl0, bl1;
                ldm_x2(bh0, bh1, sb + (nt * 8 + rowb) * 272 + bcol);
                ldm_x2(bl0, bl1, sb + FV_KB + (nt * 8 + rowb) * 272 + bcol);
                mma3(s[nt], qh[ks], ql[ks], bh0, bh1, bl0, bl1);
            }
        }

#pragma unroll
        for (int nt = 0; nt < 8; nt++) {
            const int cbm = e0 + nt * 8 + th * 2;
            float2 mk0 = *(const float2*)&mask[(size_t)r0 * S_E + cbm];
            float2 mk1 = *(const float2*)&mask[(size_t)(r0 + 8) * S_E + cbm];
            s[nt][0] = s[nt][0] * scale + mk0.x;
            s[nt][1] = s[nt][1] * scale + mk0.y;
            s[nt][2] = s[nt][2] * scale + mk1.x;
            s[nt][3] = s[nt][3] * scale + mk1.y;
        }
        float mx0 = -INFINITY, mx1 = -INFINITY;
#pragma unroll
        for (int nt = 0; nt < 8; nt++) {
            mx0 = fmaxf(mx0, fmaxf(s[nt][0], s[nt][1]));
            mx1 = fmaxf(mx1, fmaxf(s[nt][2], s[nt][3]));
        }
        mx0 = fmaxf(mx0, __shfl_xor_sync(0xffffffffu, mx0, 1));
        mx0 = fmaxf(mx0, __shfl_xor_sync(0xffffffffu, mx0, 2));
        mx1 = fmaxf(mx1, __shfl_xor_sync(0xffffffffu, mx1, 1));
        mx1 = fmaxf(mx1, __shfl_xor_sync(0xffffffffu, mx1, 2));
        float mn0 = fmaxf(m0i, mx0);
        float mn1 = fmaxf(m1i, mx1);
        float cr0 = __expf(m0i - mn0);
        float cr1 = __expf(m1i - mn1);
        m0i = mn0; m1i = mn1;
        float sm0 = 0.f, sm1 = 0.f;
#pragma unroll
        for (int nt = 0; nt < 8; nt++) {
            s[nt][0] = __expf(s[nt][0] - mn0);
            s[nt][1] = __expf(s[nt][1] - mn0);
            s[nt][2] = __expf(s[nt][2] - mn1);
            s[nt][3] = __expf(s[nt][3] - mn1);
            sm0 += s[nt][0] + s[nt][1];
            sm1 += s[nt][2] + s[nt][3];
        }
        sm0 += __shfl_xor_sync(0xffffffffu, sm0, 1);
        sm0 += __shfl_xor_sync(0xffffffffu, sm0, 2);
        sm1 += __shfl_xor_sync(0xffffffffu, sm1, 1);
        sm1 += __shfl_xor_sync(0xffffffffu, sm1, 2);
        l0i = l0i * cr0 + sm0;
        l1i = l1i * cr1 + sm1;
        if (cr0 < 1.f || cr1 < 1.f) {
#pragma unroll
            for (int nt = 0; nt < 16; nt++) {
                o[nt][0] *= cr0;
                o[nt][1] *= cr0;
                o[nt][2] *= cr1;
                o[nt][3] *= cr1;
            }
        }

#pragma unroll
        for (int ks2 = 0; ks2 < 4; ks2++) {
            unsigned phi[4], plo[4];
            const float* sa = s[2 * ks2];
            const float* sbp = s[2 * ks2 + 1];
            split2(sa[0], sa[1], phi[0], plo[0]);
            split2(sa[2], sa[3], phi[1], plo[1]);
            split2(sbp[0], sbp[1], phi[2], plo[2]);
            split2(sbp[2], sbp[3], phi[3], plo[3]);
            const int rowv = lane & 7;
            const unsigned vcol = (ks2 * 8 + ((lane >> 3) & 1) * 4) * 4;
#pragma unroll
            for (int nt2 = 0; nt2 < 16; nt2++) {
                unsigned vh0, vh1, vl0, vl1;
                ldm_x2(vh0, vh1, sb + 2 * FV_KB + (nt2 * 8 + rowv) * 144 + vcol);
                ldm_x2(vl0, vl1, sb + 2 * FV_KB + FV_VB + (nt2 * 8 + rowv) * 144 + vcol);
                mma3(o[nt2], phi, plo, vh0, vh1, vl0, vl1);
            }
        }
    }
#undef FV_ISSUE

    const float inv0 = 1.0f / l0i;
    const float inv1 = 1.0f / l1i;
#pragma unroll
    for (int nt2 = 0; nt2 < 16; nt2++) {
        const int cc = h * HD + nt2 * 8 + th * 2;
        unsigned hh, ll;
        split2(o[nt2][0] * inv0, o[nt2][1] * inv0, hh, ll);
        *(unsigned*)&AOhi[(size_t)r0 * (NH * HD) + cc] = hh;
        *(unsigned*)&AOlo[(size_t)r0 * (NH * HD) + cc] = ll;
        split2(o[nt2][2] * inv1, o[nt2][3] * inv1, hh, ll);
        *(unsigned*)&AOhi[(size_t)(r0 + 8) * (NH * HD) + cc] = hh;
        *(unsigned*)&AOlo[(size_t)(r0 + 8) * (NH * HD) + cc] = ll;
    }
}

// ---------------- launch ----------------
#define SYM(p, s) cudaGetSymbolAddress((void**)&p, s)

extern "C" void kernel_launch(void* const* d_in, const int* in_sizes, int n_in,
                              void* d_out, int out_size)
{
    const float* hs   = (const float*)d_in[0];
    const float* ehs  = (const float*)d_in[1];
    const float* mask = (const float*)d_in[2];
    const float* Wq   = (const float*)d_in[3];
    const float* bq   = (const float*)d_in[4];
    const float* Wk   = (const float*)d_in[5];
    const float* bk   = (const float*)d_in[6];
    const float* Wv   = (const float*)d_in[7];
    const float* bv   = (const float*)d_in[8];
    const float* Wo   = (const float*)d_in[9];
    const float* qn   = (const float*)d_in[10];
    const float* kn   = (const float*)d_in[11];
    float* out = (float*)d_out;

    bf16 *hsH, *hsL, *ehsH, *ehsL, *WqTH, *WqTL, *WkTH, *WkTL, *WvTH, *WvTL, *WoTH, *WoTL;
    bf16 *QH, *QL, *KH, *KL, *VTH, *VTL, *AOH, *AOL;
    SYM(hsH, g_hsH);  SYM(hsL, g_hsL);
    SYM(ehsH, g_ehsH); SYM(ehsL, g_ehsL);
    SYM(WqTH, g_WqTH); SYM(WqTL, g_WqTL);
    SYM(WkTH, g_WkTH); SYM(WkTL, g_WkTL);
    SYM(WvTH, g_WvTH); SYM(WvTL, g_WvTL);
    SYM(WoTH, g_WoTH); SYM(WoTL, g_WoTL);
    SYM(QH, g_QH); SYM(QL, g_QL);
    SYM(KH, g_KH); SYM(KL, g_KL);
    SYM(VTH, g_VTH); SYM(VTL, g_VTL);
    SYM(AOH, g_AOH); SYM(AOL, g_AOL);

    cudaFuncSetAttribute(gemm_qkv, cudaFuncAttributeMaxDynamicSharedMemorySize, GD_SMEM);
    cudaFuncSetAttribute(gemm_db, cudaFuncAttributeMaxDynamicSharedMemorySize, GD_SMEM);
    cudaFuncSetAttribute(flash_x3d, cudaFuncAttributeMaxDynamicSharedMemorySize, FV_SMEM);

    // 0: activations split
    conv_split_all<<<(NQ4 + NE4 + 255) / 256, 256>>>(hs, ehs, hsH, hsL, ehsH, ehsL);
    // 1: all weights transpose/split
    convT_all<<<dim3(64, 64, 4), 256>>>(Wq, Wk, Wv, Wo, WqTH, WqTL, WkTH, WkTL,
                                        WvTH, WvTL, WoTH, WoTL);
    // 2: merged Q+K+V projections
    gemm_qkv<<<dim3(16, 16, 2), 256, GD_SMEM>>>(hsH, hsL, ehsH, ehsL,
                                                WqTH, WqTL, bq, qn, QH, QL,
                                                WkTH, WkTL, bk, kn, KH, KL,
                                                WvTH, WvTL, bv, VTH, VTL);
    // 3: attention  (ncu profiles OUR index 3)
    flash_x3d<<<dim3(S_Q / 128, NH), 256, FV_SMEM>>>(QH, QL, KH, KL, VTH, VTL,
                                                     mask, AOH, AOL);
    // 4: output projection
    gemm_db<<<dim3(16, 16), 256, GD_SMEM>>>(AOH, AOL, WoTH, WoTL, nullptr, nullptr,
                                            out, nullptr, nullptr, H, NH * HD, 0, 0);
}

// round 17
// speedup vs baseline: 1.0623x; 1.0557x over previous
#include <cuda_runtime.h>
#include <cuda_bf16.h>
#include <stdint.h>
#include <math.h>

#define H    2048
#define NH   16
#define NKV  4
#define HD   128
#define S_Q  2048
#define S_E  4096
#define EPS  1e-6f

typedef __nv_bfloat16 bf16;
typedef __nv_bfloat162 bf162;

// ---------------- scratch ----------------
__device__ bf16 g_hsH[S_Q * H],    g_hsL[S_Q * H];
__device__ bf16 g_ehsH[S_E * H],   g_ehsL[S_E * H];
__device__ bf16 g_WqTH[H * H],     g_WqTL[H * H];
__device__ bf16 g_WkTH[512 * H],   g_WkTL[512 * H];
__device__ bf16 g_WvTH[512 * H],   g_WvTL[512 * H];
__device__ bf16 g_WoTH[H * H],     g_WoTL[H * H];
__device__ bf16 g_QH[S_Q * H],     g_QL[S_Q * H];
__device__ bf16 g_KH[S_E * 512],   g_KL[S_E * 512];
__device__ bf16 g_VTH[512 * S_E],  g_VTL[512 * S_E];
__device__ bf16 g_AOH[S_Q * H],    g_AOL[S_Q * H];

// ---------------- helpers ----------------
__device__ __forceinline__ unsigned smaddr(const void* p) {
    return (unsigned)__cvta_generic_to_shared(p);
}
__device__ __forceinline__ void ldm_x4(unsigned& r0, unsigned& r1, unsigned& r2, unsigned& r3,
                                       unsigned addr) {
    asm volatile("ldmatrix.sync.aligned.m8n8.x4.shared.b16 {%0,%1,%2,%3},[%4];\n"
                 : "=r"(r0), "=r"(r1), "=r"(r2), "=r"(r3) : "r"(addr));
}
__device__ __forceinline__ void mma16816(float* c, unsigned a0, unsigned a1, unsigned a2,
                                         unsigned a3, unsigned b0, unsigned b1) {
    asm volatile(
        "mma.sync.aligned.m16n8k16.row.col.f32.bf16.bf16.f32 "
        "{%0,%1,%2,%3},{%4,%5,%6,%7},{%8,%9},{%0,%1,%2,%3};\n"
        : "+f"(c[0]), "+f"(c[1]), "+f"(c[2]), "+f"(c[3])
        : "r"(a0), "r"(a1), "r"(a2), "r"(a3), "r"(b0), "r"(b1));
}
__device__ __forceinline__ void mma3(float* c, const unsigned* ah, const unsigned* al,
                                     unsigned bh0, unsigned bh1, unsigned bl0, unsigned bl1) {
    mma16816(c, ah[0], ah[1], ah[2], ah[3], bh0, bh1);
    mma16816(c, ah[0], ah[1], ah[2], ah[3], bl0, bl1);
    mma16816(c, al[0], al[1], al[2], al[3], bh0, bh1);
}
__device__ __forceinline__ void split2(float x, float y, unsigned& hi, unsigned& lo) {
    bf162 h; h.x = __float2bfloat16(x); h.y = __float2bfloat16(y);
    bf162 l; l.x = __float2bfloat16(x - __bfloat162float(h.x));
    l.y = __float2bfloat16(y - __bfloat162float(h.y));
    hi = *(unsigned*)&h; lo = *(unsigned*)&l;
}
__device__ __forceinline__ void cp16(unsigned saddr, const void* g) {
    asm volatile("cp.async.cg.shared.global [%0], [%1], 16;" :: "r"(saddr), "l"(g));
}
#define CP_COMMIT() asm volatile("cp.async.commit_group;" ::: "memory")
#define CP_WAIT1()  asm volatile("cp.async.wait_group 1;" ::: "memory")

// ---------------- prepass 1 ----------------
#define NQ4 (S_Q * H / 4)
#define NE4 (S_E * H / 4)
__global__ __launch_bounds__(256) void conv_split_all(
    const float* __restrict__ hs, const float* __restrict__ ehs,
    bf16* __restrict__ hsH, bf16* __restrict__ hsL,
    bf16* __restrict__ ehsH, bf16* __restrict__ ehsL)
{
    int i = blockIdx.x * 256 + threadIdx.x;
    const float* X; bf16 *Xh, *Xl;
    if (i < NQ4) { X = hs; Xh = hsH; Xl = hsL; }
    else { i -= NQ4; if (i >= NE4) return; X = ehs; Xh = ehsH; Xl = ehsL; }
    float4 v = *(const float4*)&X[(size_t)i * 4];
    unsigned h0, l0, h1, l1;
    split2(v.x, v.y, h0, l0);
    split2(v.z, v.w, h1, l1);
    float2 ho, lo;
    ((unsigned*)&ho)[0] = h0; ((unsigned*)&ho)[1] = h1;
    ((unsigned*)&lo)[0] = l0; ((unsigned*)&lo)[1] = l1;
    *(float2*)&Xh[(size_t)i * 4] = ho;
    *(float2*)&Xl[(size_t)i * 4] = lo;
}

// ---------------- prepass 2 ----------------
__global__ __launch_bounds__(256) void convT_all(
    const float* __restrict__ Wq, const float* __restrict__ Wk,
    const float* __restrict__ Wv, const float* __restrict__ Wo,
    bf16* __restrict__ qTh, bf16* __restrict__ qTl,
    bf16* __restrict__ kTh, bf16* __restrict__ kTl,
    bf16* __restrict__ vTh, bf16* __restrict__ vTl,
    bf16* __restrict__ oTh, bf16* __restrict__ oTl)
{
    const float* W; bf16 *Th, *Tl; int N;
    switch (blockIdx.z) {
        case 0: W = Wq; Th = qTh; Tl = qTl; N = 2048; break;
        case 1: W = Wk; Th = kTh; Tl = kTl; N = 512; break;
        case 2: W = Wv; Th = vTh; Tl = vTl; N = 512; break;
        default: W = Wo; Th = oTh; Tl = oTl; N = 2048; break;
    }
    const int n0 = blockIdx.x * 32;
    if (n0 >= N) return;
    const int k0 = blockIdx.y * 32;
    __shared__ float t[32][33];
    const int tx = threadIdx.x & 31;
    const int ty = threadIdx.x >> 5;
#pragma unroll
    for (int i = 0; i < 4; i++)
        t[ty + 8 * i][tx] = W[(size_t)(k0 + ty + 8 * i) * N + n0 + tx];
    __syncthreads();
#pragma unroll
    for (int i = 0; i < 4; i++) {
        int n = ty + 8 * i;
        float v = t[tx][n];
        bf16 h = __float2bfloat16(v);
        Th[(size_t)(n0 + n) * H + k0 + tx] = h;
        Tl[(size_t)(n0 + n) * H + k0 + tx] = __float2bfloat16(v - __bfloat162float(h));
    }
}

// ---------------- GEMM core ----------------
#define GD_STG  40960
#define GD_SMEM (2 * GD_STG)

__device__ __forceinline__ void gemm_core(
    const bf16* __restrict__ Ahi, const bf16* __restrict__ Alo,
    const bf16* __restrict__ Bhi, const bf16* __restrict__ Blo,
    const float* __restrict__ bias, const float* __restrict__ nw,
    float* __restrict__ Cf, bf16* __restrict__ Chi, bf16* __restrict__ Clo,
    int N, int K, int mode, int vt_stride, int m0, int n0, char* smc, float* ssq)
{
    const unsigned su = smaddr(smc);
    const int tid  = threadIdx.x;
    const int lane = tid & 31;
    const int warp = tid >> 5;
    const int wm   = warp >> 2;
    const int wn   = warp & 3;
    const int g    = lane >> 2;
    const int th   = lane & 3;

    const int lrow  = tid >> 1;
    const int lhalf = (tid & 1) * 32;
    const size_t gA = (size_t)(m0 + lrow) * K + lhalf / 2;
    const size_t gB = (size_t)(n0 + lrow) * K + lhalf / 2;
    const unsigned soff = lrow * 80 + lhalf;

#define GD_ISSUE(slot, kt) do {                                  \
        unsigned sb_ = su + (slot) * GD_STG;                     \
        size_t ko_ = (size_t)(kt) * 32;                          \
        cp16(sb_ + soff,              Ahi + gA + ko_);           \
        cp16(sb_ + soff + 16,         Ahi + gA + ko_ + 8);       \
        cp16(sb_ + 10240 + soff,      Alo + gA + ko_);           \
        cp16(sb_ + 10240 + soff + 16, Alo + gA + ko_ + 8);       \
        cp16(sb_ + 20480 + soff,      Bhi + gB + ko_);           \
        cp16(sb_ + 20480 + soff + 16, Bhi + gB + ko_ + 8);       \
        cp16(sb_ + 30720 + soff,      Blo + gB + ko_);           \
        cp16(sb_ + 30720 + soff + 16, Blo + gB + ko_ + 8);       \
    } while (0)

    float acc[4][4][4];
#pragma unroll
    for (int i = 0; i < 4; i++)
#pragma unroll
        for (int j = 0; j < 4; j++)
#pragma unroll
            for (int c = 0; c < 4; c++) acc[i][j][c] = 0.f;

    GD_ISSUE(0, 0); CP_COMMIT();
    GD_ISSUE(1, 1); CP_COMMIT();

    const int q4 = lane >> 3;
    const unsigned brow = (unsigned)((q4 >> 1) * 8 + (lane & 7));
    const unsigned bhalf = (q4 & 1) * 16;

    const int nK = K / 32;
    for (int kt = 0; kt < nK; kt++) {
        CP_WAIT1();
        __syncthreads();
        const unsigned sb = su + (kt & 1) * GD_STG;
#pragma unroll
        for (int ks = 0; ks < 2; ks++) {
            unsigned ahi[4][4], alo[4][4];
            const int rowl = wm * 64 + (lane & 15);
            const unsigned acol = (ks * 8 + (lane >> 4) * 4) * 4;
#pragma unroll
            for (int mt = 0; mt < 4; mt++) {
                ldm_x4(ahi[mt][0], ahi[mt][1], ahi[mt][2], ahi[mt][3],
                       sb + (rowl + mt * 16) * 80 + acol);
                ldm_x4(alo[mt][0], alo[mt][1], alo[mt][2], alo[mt][3],
                       sb + 10240 + (rowl + mt * 16) * 80 + acol);
            }
#pragma unroll
            for (int ntp = 0; ntp < 2; ntp++) {
                unsigned addr = sb + 20480 + (wn * 32 + ntp * 16 + brow) * 80 + ks * 32 + bhalf;
                unsigned bh0, bh1, bh2, bh3, bl0, bl1, bl2, bl3;
                ldm_x4(bh0, bh1, bh2, bh3, addr);
                ldm_x4(bl0, bl1, bl2, bl3, addr + 10240);
#pragma unroll
                for (int mt = 0; mt < 4; mt++) {
                    mma3(acc[mt][2 * ntp],     ahi[mt], alo[mt], bh0, bh1, bl0, bl1);
                    mma3(acc[mt][2 * ntp + 1], ahi[mt], alo[mt], bh2, bh3, bl2, bl3);
                }
            }
        }
        __syncthreads();
        if (kt + 2 < nK) GD_ISSUE(kt & 1, kt + 2);
        CP_COMMIT();
    }
#undef GD_ISSUE

    if (bias) {
#pragma unroll
        for (int nt = 0; nt < 4; nt++) {
            int cc = n0 + wn * 32 + nt * 8 + th * 2;
            float b0 = bias[cc], b1 = bias[cc + 1];
#pragma unroll
            for (int mt = 0; mt < 4; mt++) {
                acc[mt][nt][0] += b0; acc[mt][nt][1] += b1;
                acc[mt][nt][2] += b0; acc[mt][nt][3] += b1;
            }
        }
    }

    if (mode == 0) {
#pragma unroll
        for (int mt = 0; mt < 4; mt++) {
            int r0 = m0 + wm * 64 + mt * 16 + g;
#pragma unroll
            for (int nt = 0; nt < 4; nt++) {
                int cc = n0 + wn * 32 + nt * 8 + th * 2;
                *(float2*)&Cf[(size_t)r0 * N + cc] = make_float2(acc[mt][nt][0], acc[mt][nt][1]);
                *(float2*)&Cf[(size_t)(r0 + 8) * N + cc] = make_float2(acc[mt][nt][2], acc[mt][nt][3]);
            }
        }
    } else if (mode == 1) {
        if (tid < 128) ssq[tid] = 0.f;
        __syncthreads();
#pragma unroll
        for (int mt = 0; mt < 4; mt++) {
            int rl = wm * 64 + mt * 16 + g;
            float p0 = 0.f, p1 = 0.f;
#pragma unroll
            for (int nt = 0; nt < 4; nt++) {
                p0 += acc[mt][nt][0] * acc[mt][nt][0] + acc[mt][nt][1] * acc[mt][nt][1];
                p1 += acc[mt][nt][2] * acc[mt][nt][2] + acc[mt][nt][3] * acc[mt][nt][3];
            }
            atomicAdd(&ssq[rl], p0);
            atomicAdd(&ssq[rl + 8], p1);
        }
        __syncthreads();
#pragma unroll
        for (int mt = 0; mt < 4; mt++) {
            int rl = wm * 64 + mt * 16 + g;
            float inv0 = rsqrtf(ssq[rl] * (1.0f / HD) + EPS);
            float inv1 = rsqrtf(ssq[rl + 8] * (1.0f / HD) + EPS);
#pragma unroll
            for (int nt = 0; nt < 4; nt++) {
                int col = wn * 32 + nt * 8 + th * 2;
                float w0 = nw[col], w1 = nw[col + 1];
                unsigned hh, ll;
                split2(acc[mt][nt][0] * inv0 * w0, acc[mt][nt][1] * inv0 * w1, hh, ll);
                *(unsigned*)&Chi[(size_t)(m0 + rl) * N + n0 + col] = hh;
                *(unsigned*)&Clo[(size_t)(m0 + rl) * N + n0 + col] = ll;
                split2(acc[mt][nt][2] * inv1 * w0, acc[mt][nt][3] * inv1 * w1, hh, ll);
                *(unsigned*)&Chi[(size_t)(m0 + rl + 8) * N + n0 + col] = hh;
                *(unsigned*)&Clo[(size_t)(m0 + rl + 8) * N + n0 + col] = ll;
            }
        }
    } else {
#pragma unroll
        for (int mt = 0; mt < 4; mt++) {
            int r0 = m0 + wm * 64 + mt * 16 + g;
#pragma unroll
            for (int nt = 0; nt < 4; nt++) {
                int cn = n0 + wn * 32 + nt * 8 + th * 2;
#pragma unroll
                for (int j = 0; j < 2; j++) {
                    float v0 = acc[mt][nt][j];
                    float v1 = acc[mt][nt][2 + j];
                    bf16 h0 = __float2bfloat16(v0);
                    bf16 h1 = __float2bfloat16(v1);
                    Chi[(size_t)(cn + j) * vt_stride + r0] = h0;
                    Chi[(size_t)(cn + j) * vt_stride + r0 + 8] = h1;
                    Clo[(size_t)(cn + j) * vt_stride + r0] =
                        __float2bfloat16(v0 - __bfloat162float(h0));
                    Clo[(size_t)(cn + j) * vt_stride + r0 + 8] =
                        __float2bfloat16(v1 - __bfloat162float(h1));
                }
            }
        }
    }
}

// ---------------- merged Q+K+V projection ----------------
__global__ __launch_bounds__(256, 2) void gemm_qkv(
    const bf16* hsH, const bf16* hsL, const bf16* ehsH, const bf16* ehsL,
    const bf16* WqTH, const bf16* WqTL, const float* bq, const float* qn,
    bf16* QH, bf16* QL,
    const bf16* WkTH, const bf16* WkTL, const float* bk, const float* kn,
    bf16* KH, bf16* KL,
    const bf16* WvTH, const bf16* WvTL, const float* bv,
    bf16* VTH, bf16* VTL)
{
    extern __shared__ char smc[];
    __shared__ float ssq[128];
    if (blockIdx.z == 0) {
        gemm_core(hsH, hsL, WqTH, WqTL, bq, qn, nullptr, QH, QL,
                  H, H, 1, 0, blockIdx.y * 128, blockIdx.x * 128, smc, ssq);
    } else {
        int bid = blockIdx.y * 16 + blockIdx.x;
        int m0 = ((bid & 127) >> 2) * 128;
        int n0 = (bid & 3) * 128;
        if (bid < 128)
            gemm_core(ehsH, ehsL, WkTH, WkTL, bk, kn, nullptr, KH, KL,
                      512, H, 1, 0, m0, n0, smc, ssq);
        else
            gemm_core(ehsH, ehsL, WvTH, WvTL, bv, nullptr, nullptr, VTH, VTL,
                      512, H, 2, S_E, m0, n0, smc, ssq);
    }
}

__global__ __launch_bounds__(256, 2) void gemm_db(
    const bf16* Ahi, const bf16* Alo, const bf16* Bhi, const bf16* Blo,
    const float* bias, const float* nw,
    float* Cf, bf16* Chi, bf16* Clo,
    int N, int K, int mode, int vt_stride)
{
    extern __shared__ char smc[];
    __shared__ float ssq[128];
    gemm_core(Ahi, Alo, Bhi, Blo, bias, nw, Cf, Chi, Clo, N, K, mode, vt_stride,
              blockIdx.y * 128, blockIdx.x * 128, smc, ssq);
}

// ---------------- flash: 2-slot cp.async (K,V,mask), x4 ldmatrix, Q in regs ----------------
#define FV_KB   17408
#define FV_VB   18432
#define FV_MOFF (2 * FV_KB + 2 * FV_VB)          // 71680
#define FV_MPITCH 272                            // 16B-aligned mask row pitch
#define FV_MB   (128 * FV_MPITCH)                // 34816
#define FV_STG  (FV_MOFF + FV_MB)                // 106496
#define FV_SMEM (2 * FV_STG)                     // 212992
#define FV_NT   (S_E / 64)

__global__ __launch_bounds__(256, 1) void flash_x3e(
    const bf16* __restrict__ Qhi, const bf16* __restrict__ Qlo,
    const bf16* __restrict__ Khi, const bf16* __restrict__ Klo,
    const bf16* __restrict__ VThi, const bf16* __restrict__ VTlo,
    const float* __restrict__ mask,
    bf16* __restrict__ AOhi, bf16* __restrict__ AOlo)
{
    extern __shared__ char smf[];
    const unsigned su = smaddr(smf);
    const int h  = blockIdx.y;
    const int kh = h >> 2;
    const int q0 = blockIdx.x * 128;
    const int tid  = threadIdx.x;
    const int lane = tid & 31;
    const int w    = tid >> 5;
    const int g    = lane >> 2;
    const int th   = lane & 3;

#define FV_ISSUE(slot, et) do {                                             \
        const unsigned sb_ = su + (slot) * FV_STG;                          \
        const int e0_ = (et) * 64;                                          \
        _Pragma("unroll")                                                   \
        for (int l = 0; l < 4; l++) {                                       \
            int ch = l * 256 + tid;                                         \
            int kr = ch >> 4, kc = ch & 15;                                 \
            size_t gk = (size_t)(e0_ + kr) * 512 + kh * 128 + kc * 8;       \
            cp16(sb_ + kr * 272 + kc * 16,          Khi + gk);              \
            cp16(sb_ + FV_KB + kr * 272 + kc * 16,  Klo + gk);              \
            int vr = ch >> 3, vc = ch & 7;                                  \
            size_t gv = (size_t)(kh * 128 + vr) * S_E + e0_ + vc * 8;       \
            cp16(sb_ + 2 * FV_KB + vr * 144 + vc * 16,         VThi + gv);  \
            cp16(sb_ + 2 * FV_KB + FV_VB + vr * 144 + vc * 16, VTlo + gv);  \
        }                                                                   \
        _Pragma("unroll")                                                   \
        for (int l = 0; l < 8; l++) {                                       \
            int ch = l * 256 + tid;                                         \
            int mr = ch >> 4, mc = ch & 15;                                 \
            cp16(sb_ + FV_MOFF + mr * FV_MPITCH + mc * 16,                  \
                 mask + (size_t)(q0 + mr) * S_E + e0_ + mc * 4);            \
        }                                                                   \
    } while (0)

    FV_ISSUE(0, 0); CP_COMMIT();
    FV_ISSUE(1, 1); CP_COMMIT();

    unsigned qh[8][4], ql[8][4];
    {
        const size_t rq0 = (size_t)(q0 + w * 16 + g) * (NH * HD) + h * HD;
        const size_t rq8 = rq0 + (size_t)8 * (NH * HD);
#pragma unroll
        for (int ks = 0; ks < 8; ks++) {
            const int c = ks * 16 + th * 2;
            qh[ks][0] = *(const unsigned*)&Qhi[rq0 + c];
            qh[ks][1] = *(const unsigned*)&Qhi[rq8 + c];
            qh[ks][2] = *(const unsigned*)&Qhi[rq0 + c + 8];
            qh[ks][3] = *(const unsigned*)&Qhi[rq8 + c + 8];
            ql[ks][0] = *(const unsigned*)&Qlo[rq0 + c];
            ql[ks][1] = *(const unsigned*)&Qlo[rq8 + c];
            ql[ks][2] = *(const unsigned*)&Qlo[rq0 + c + 8];
            ql[ks][3] = *(const unsigned*)&Qlo[rq8 + c + 8];
        }
    }

    const float scale = 0.08838834764831845f;
    float o[16][4];
    float m0i = -INFINITY, m1i = -INFINITY, l0i = 0.f, l1i = 0.f;
#pragma unroll
    for (int nt = 0; nt < 16; nt++)
#pragma unroll
        for (int c = 0; c < 4; c++) o[nt][c] = 0.f;

    const int r0 = q0 + w * 16 + g;
    const int q4 = lane >> 3;
    const unsigned frow = (unsigned)((q4 >> 1) * 8 + (lane & 7));
    const unsigned fhalf = (q4 & 1) * 16;

    for (int et = 0; et < FV_NT; et++) {
        CP_WAIT1();
        __syncthreads();
        const unsigned sb = su + (et & 1) * FV_STG;
        const unsigned mrow0 = (et & 1) * FV_STG + FV_MOFF + (w * 16 + g) * FV_MPITCH;

        // ---- S = Q K^T (x4 ldmatrix, nt pairs) ----
        float s[8][4];
#pragma unroll
        for (int nt = 0; nt < 8; nt++)
#pragma unroll
            for (int c = 0; c < 4; c++) s[nt][c] = 0.f;

#pragma unroll
        for (int ks = 0; ks < 8; ks++) {
#pragma unroll
            for (int ntp = 0; ntp < 4; ntp++) {
                unsigned addr = sb + (ntp * 16 + frow) * 272 + ks * 32 + fhalf;
                unsigned b0, b1, b2, b3, c0, c1, c2, c3;
                ldm_x4(b0, b1, b2, b3, addr);
                ldm_x4(c0, c1, c2, c3, addr + FV_KB);
                mma3(s[2 * ntp],     qh[ks], ql[ks], b0, b1, c0, c1);
                mma3(s[2 * ntp + 1], qh[ks], ql[ks], b2, b3, c2, c3);
            }
        }

        // ---- scale + mask(smem) + online softmax ----
#pragma unroll
        for (int nt = 0; nt < 8; nt++) {
            const unsigned mo = (nt * 8 + th * 2) * 4;
            float2 mk0 = *(const float2*)&smf[mrow0 + mo];
            float2 mk1 = *(const float2*)&smf[mrow0 + 8 * FV_MPITCH + mo];
            s[nt][0] = s[nt][0] * scale + mk0.x;
            s[nt][1] = s[nt][1] * scale + mk0.y;
            s[nt][2] = s[nt][2] * scale + mk1.x;
            s[nt][3] = s[nt][3] * scale + mk1.y;
        }
        float mx0 = -INFINITY, mx1 = -INFINITY;
#pragma unroll
        for (int nt = 0; nt < 8; nt++) {
            mx0 = fmaxf(mx0, fmaxf(s[nt][0], s[nt][1]));
            mx1 = fmaxf(mx1, fmaxf(s[nt][2], s[nt][3]));
        }
        mx0 = fmaxf(mx0, __shfl_xor_sync(0xffffffffu, mx0, 1));
        mx0 = fmaxf(mx0, __shfl_xor_sync(0xffffffffu, mx0, 2));
        mx1 = fmaxf(mx1, __shfl_xor_sync(0xffffffffu, mx1, 1));
        mx1 = fmaxf(mx1, __shfl_xor_sync(0xffffffffu, mx1, 2));
        float mn0 = fmaxf(m0i, mx0);
        float mn1 = fmaxf(m1i, mx1);
        float cr0 = __expf(m0i - mn0);
        float cr1 = __expf(m1i - mn1);
        m0i = mn0; m1i = mn1;
        float sm0 = 0.f, sm1 = 0.f;
#pragma unroll
        for (int nt = 0; nt < 8; nt++) {
            s[nt][0] = __expf(s[nt][0] - mn0);
            s[nt][1] = __expf(s[nt][1] - mn0);
            s[nt][2] = __expf(s[nt][2] - mn1);
            s[nt][3] = __expf(s[nt][3] - mn1);
            sm0 += s[nt][0] + s[nt][1];
            sm1 += s[nt][2] + s[nt][3];
        }
        sm0 += __shfl_xor_sync(0xffffffffu, sm0, 1);
        sm0 += __shfl_xor_sync(0xffffffffu, sm0, 2);
        sm1 += __shfl_xor_sync(0xffffffffu, sm1, 1);
        sm1 += __shfl_xor_sync(0xffffffffu, sm1, 2);
        l0i = l0i * cr0 + sm0;
        l1i = l1i * cr1 + sm1;
        if (cr0 < 1.f || cr1 < 1.f) {
#pragma unroll
            for (int nt = 0; nt < 16; nt++) {
                o[nt][0] *= cr0;
                o[nt][1] *= cr0;
                o[nt][2] *= cr1;
                o[nt][3] *= cr1;
            }
        }

        // ---- O += P V (x4 ldmatrix, nt pairs) ----
#pragma unroll
        for (int ks2 = 0; ks2 < 4; ks2++) {
            unsigned phi[4], plo[4];
            const float* sa = s[2 * ks2];
            const float* sbp = s[2 * ks2 + 1];
            split2(sa[0], sa[1], phi[0], plo[0]);
            split2(sa[2], sa[3], phi[1], plo[1]);
            split2(sbp[0], sbp[1], phi[2], plo[2]);
            split2(sbp[2], sbp[3], phi[3], plo[3]);
#pragma unroll
            for (int ntp = 0; ntp < 8; ntp++) {
                unsigned addr = sb + 2 * FV_KB + (ntp * 16 + frow) * 144 + ks2 * 32 + fhalf;
                unsigned v0, v1, v2, v3, u0, u1, u2, u3;
                ldm_x4(v0, v1, v2, v3, addr);
                ldm_x4(u0, u1, u2, u3, addr + FV_VB);
                mma3(o[2 * ntp],     phi, plo, v0, v1, u0, u1);
                mma3(o[2 * ntp + 1], phi, plo, v2, v3, u2, u3);
            }
        }

        __syncthreads();
        if (et + 2 < FV_NT) FV_ISSUE(et & 1, et + 2);
        CP_COMMIT();
    }
#undef FV_ISSUE

    const float inv0 = 1.0f / l0i;
    const float inv1 = 1.0f / l1i;
#pragma unroll
    for (int nt2 = 0; nt2 < 16; nt2++) {
        const int cc = h * HD + nt2 * 8 + th * 2;
        unsigned hh, ll;
        split2(o[nt2][0] * inv0, o[nt2][1] * inv0, hh, ll);
        *(unsigned*)&AOhi[(size_t)r0 * (NH * HD) + cc] = hh;
        *(unsigned*)&AOlo[(size_t)r0 * (NH * HD) + cc] = ll;
        split2(o[nt2][2] * inv1, o[nt2][3] * inv1, hh, ll);
        *(unsigned*)&AOhi[(size_t)(r0 + 8) * (NH * HD) + cc] = hh;
        *(unsigned*)&AOlo[(size_t)(r0 + 8) * (NH * HD) + cc] = ll;
    }
}

// ---------------- launch ----------------
#define SYM(p, s) cudaGetSymbolAddress((void**)&p, s)

extern "C" void kernel_launch(void* const* d_in, const int* in_sizes, int n_in,
                              void* d_out, int out_size)
{
    const float* hs   = (const float*)d_in[0];
    const float* ehs  = (const float*)d_in[1];
    const float* mask = (const float*)d_in[2];
    const float* Wq   = (const float*)d_in[3];
    const float* bq   = (const float*)d_in[4];
    const float* Wk   = (const float*)d_in[5];
    const float* bk   = (const float*)d_in[6];
    const float* Wv   = (const float*)d_in[7];
    const float* bv   = (const float*)d_in[8];
    const float* Wo   = (const float*)d_in[9];
    const float* qn   = (const float*)d_in[10];
    const float* kn   = (const float*)d_in[11];
    float* out = (float*)d_out;

    bf16 *hsH, *hsL, *ehsH, *ehsL, *WqTH, *WqTL, *WkTH, *WkTL, *WvTH, *WvTL, *WoTH, *WoTL;
    bf16 *QH, *QL, *KH, *KL, *VTH, *VTL, *AOH, *AOL;
    SYM(hsH, g_hsH);  SYM(hsL, g_hsL);
    SYM(ehsH, g_ehsH); SYM(ehsL, g_ehsL);
    SYM(WqTH, g_WqTH); SYM(WqTL, g_WqTL);
    SYM(WkTH, g_WkTH); SYM(WkTL, g_WkTL);
    SYM(WvTH, g_WvTH); SYM(WvTL, g_WvTL);
    SYM(WoTH, g_WoTH); SYM(WoTL, g_WoTL);
    SYM(QH, g_QH); SYM(QL, g_QL);
    SYM(KH, g_KH); SYM(KL, g_KL);
    SYM(VTH, g_VTH); SYM(VTL, g_VTL);
    SYM(AOH, g_AOH); SYM(AOL, g_AOL);

    cudaFuncSetAttribute(gemm_qkv, cudaFuncAttributeMaxDynamicSharedMemorySize, GD_SMEM);
    cudaFuncSetAttribute(gemm_db, cudaFuncAttributeMaxDynamicSharedMemorySize, GD_SMEM);
    cudaFuncSetAttribute(flash_x3e, cudaFuncAttributeMaxDynamicSharedMemorySize, FV_SMEM);

    // 0: activations split
    conv_split_all<<<(NQ4 + NE4 + 255) / 256, 256>>>(hs, ehs, hsH, hsL, ehsH, ehsL);
    // 1: weights transpose/split
    convT_all<<<dim3(64, 64, 4), 256>>>(Wq, Wk, Wv, Wo, WqTH, WqTL, WkTH, WkTL,
                                        WvTH, WvTL, WoTH, WoTL);
    // 2: merged Q+K+V projections
    gemm_qkv<<<dim3(16, 16, 2), 256, GD_SMEM>>>(hsH, hsL, ehsH, ehsL,
                                                WqTH, WqTL, bq, qn, QH, QL,
                                                WkTH, WkTL, bk, kn, KH, KL,
                                                WvTH, WvTL, bv, VTH, VTL);
    // 3: attention (ncu profiles our index 3)
    flash_x3e<<<dim3(S_Q / 128, NH), 256, FV_SMEM>>>(QH, QL, KH, KL, VTH, VTL,
                                                     mask, AOH, AOL);
    // 4: output projection
    gemm_db<<<dim3(16, 16), 256, GD_SMEM>>>(AOH, AOL, WoTH, WoTL, nullptr, nullptr,
                                            out, nullptr, nullptr, H, NH * HD, 0, 0);
}